// round 8
// baseline (speedup 1.0000x reference)
#include <cuda_runtime.h>
#include <cuda_fp16.h>
#include <cstdint>

// SimpleCodebook VQ, R8: 1-product fp16 HMMA approx pass with deep HMMA
// windows (64x64 warp tile) + register fragment ping-pong across ks-steps,
// + exact fp64 rescore of rare ambiguous rows.

#define NQ 8192
#define NC 8192
#define DD 512
#define BMT 128             // CTA tile M
#define BNT 256             // CTA tile N
#define BK  64              // K chunk (fp16) -> 128B rows
#define NKC (DD / BK)       // 8
#define NCHUNK (NC / BNT)   // 32
#define DELTA 0.5f

#define NSTG 3
#define STG_BYTES 49152     // A(16K) + B(32K)
#define OFF_ESQ 0           // 256 floats = 1KB
#define OFF_RED 1024        // 4 arrays x 128x4 x 4B = 8KB
#define OFF_STG 9216
#define SMEM_TOTAL (OFF_STG + NSTG * STG_BYTES)   // 156672 -> 1 CTA/SM

// ---- device global scratch ----
__device__ __half g_X0[NQ * DD];
__device__ __half g_E0[NC * DD];
__device__ float  g_esq[NC];
__device__ float4 g_cand[NCHUNK * NQ];   // (v1, idx1_bits, v2, idx2_bits)

static __device__ __forceinline__ uint32_t smem_u32(const void* p) {
    uint32_t a;
    asm("{ .reg .u64 t; cvta.to.shared.u64 t, %1; cvt.u32.u64 %0, t; }" : "=r"(a) : "l"(p));
    return a;
}
static __device__ __forceinline__ uint32_t swz(uint32_t o) { return o ^ ((o >> 3) & 0x70); }

static __device__ __forceinline__ void cp16(uint32_t dst, const void* src) {
    asm volatile("cp.async.cg.shared.global [%0], [%1], 16;" :: "r"(dst), "l"(src) : "memory");
}
#define CP_COMMIT() asm volatile("cp.async.commit_group;" ::: "memory")
#define CP_WAIT0()  asm volatile("cp.async.wait_group 0;" ::: "memory")
#define CP_WAIT1()  asm volatile("cp.async.wait_group 1;" ::: "memory")

static __device__ __forceinline__ void ldsm_x4(uint32_t* r, uint32_t addr) {
    asm volatile("ldmatrix.sync.aligned.m8n8.x4.shared.b16 {%0,%1,%2,%3}, [%4];"
                 : "=r"(r[0]), "=r"(r[1]), "=r"(r[2]), "=r"(r[3]) : "r"(addr));
}
static __device__ __forceinline__ void hmma(float* c, const uint32_t* a, const uint32_t* b) {
    asm volatile(
        "mma.sync.aligned.m16n8k16.row.col.f32.f16.f16.f32 "
        "{%0,%1,%2,%3}, {%4,%5,%6,%7}, {%8,%9}, {%0,%1,%2,%3};"
        : "+f"(c[0]), "+f"(c[1]), "+f"(c[2]), "+f"(c[3])
        : "r"(a[0]), "r"(a[1]), "r"(a[2]), "r"(a[3]), "r"(b[0]), "r"(b[1]));
}

// ---------------------------------------------------------------------------
// Kernel 1: X0 = fp16(2x), E0 = fp16(e), esq = ||e||^2 (fp32)
// ---------------------------------------------------------------------------
__global__ void convert_kernel(const float* __restrict__ X, const float* __restrict__ E) {
    int row = blockIdx.x;
    int t = threadIdx.x;                     // 128
    size_t base = (size_t)row * DD + t * 4;
    {
        float4 v = *reinterpret_cast<const float4*>(X + base);
        __half2 h01 = __floats2half2_rn(2.f * v.x, 2.f * v.y);
        __half2 h23 = __floats2half2_rn(2.f * v.z, 2.f * v.w);
        *reinterpret_cast<__half2*>(&g_X0[base])     = h01;
        *reinterpret_cast<__half2*>(&g_X0[base + 2]) = h23;
    }
    {
        float4 v = *reinterpret_cast<const float4*>(E + base);
        __half2 h01 = __floats2half2_rn(v.x, v.y);
        __half2 h23 = __floats2half2_rn(v.z, v.w);
        *reinterpret_cast<__half2*>(&g_E0[base])     = h01;
        *reinterpret_cast<__half2*>(&g_E0[base + 2]) = h23;

        float sq = v.x * v.x + v.y * v.y + v.z * v.z + v.w * v.w;
        #pragma unroll
        for (int o = 16; o; o >>= 1) sq += __shfl_down_sync(0xFFFFFFFFu, sq, o);
        __shared__ float ws[4];
        if ((t & 31) == 0) ws[t >> 5] = sq;
        __syncthreads();
        if (t == 0) g_esq[row] = ws[0] + ws[1] + ws[2] + ws[3];
    }
}

// ---------------------------------------------------------------------------
// Kernel 2: approx HMMA GEMM + top-2 per (row, chunk). grid (64,32), 256 thr.
// ---------------------------------------------------------------------------
static __device__ __forceinline__ void load_stage(uint32_t sb, int s, int kc,
                                                  int m0, int cb0, int tid) {
    uint32_t stg = sb + OFF_STG + s * STG_BYTES;
    // A: 128 rows x 64 cols
    #pragma unroll
    for (int i = 0; i < 4; i++) {
        int cid = tid + i * 256;              // 0..1023
        int row = cid >> 3;
        int c16 = cid & 7;
        const __half* src = g_X0 + (size_t)(m0 + row) * DD + kc * BK + c16 * 8;
        cp16(stg + swz((uint32_t)(row * 128 + c16 * 16)), src);
    }
    // B: 256 rows x 64 cols
    #pragma unroll
    for (int i = 0; i < 8; i++) {
        int cid = tid + i * 256;              // 0..2047
        int row = cid >> 3;
        int c16 = cid & 7;
        const __half* src = g_E0 + (size_t)(cb0 + row) * DD + kc * BK + c16 * 8;
        cp16(stg + 16384 + swz((uint32_t)(row * 128 + c16 * 16)), src);
    }
    CP_COMMIT();
}

static __device__ __forceinline__ void upd2(float v, int i, float& v1, int& i1,
                                            float& v2, int& i2) {
    if (v > v1 || (v == v1 && i < i1)) {
        v2 = v1; i2 = i1; v1 = v; i1 = i;
    } else if (v > v2 || (v == v2 && i < i2)) {
        v2 = v; i2 = i;
    }
}

__global__ __launch_bounds__(256, 1)
void vq_mma_kernel() {
    extern __shared__ char smem[];
    const uint32_t sb = smem_u32(smem);
    const int tid = threadIdx.x;
    const int lane = tid & 31;
    const int wid = tid >> 5;
    const int warp_m = wid >> 2;         // 0..1  (64 rows each)
    const int warp_n = wid & 3;          // 0..3  (64 cols each)
    const int m0 = blockIdx.x * BMT;
    const int cb0 = blockIdx.y * BNT;

    float* es = reinterpret_cast<float*>(smem + OFF_ESQ);
    for (int i = tid; i < BNT; i += 256) es[i] = g_esq[cb0 + i];

    float acc[4][8][4];
    #pragma unroll
    for (int mf = 0; mf < 4; mf++)
        #pragma unroll
        for (int nf = 0; nf < 8; nf++)
            #pragma unroll
            for (int c = 0; c < 4; c++) acc[mf][nf][c] = 0.f;

    // hoisted swizzle: addr = stg + base + (k ^ m), m = ((row*128)>>3)&0x70
    const uint32_t a_row = (uint32_t)(warp_m * 64 + (lane & 15));
    const uint32_t a_kb  = (uint32_t)((lane >> 4) * 16);
    const uint32_t b_row = (uint32_t)(warp_n * 64 + (lane >> 4) * 8 + (lane & 7));
    const uint32_t b_kb  = (uint32_t)(((lane >> 3) & 1) * 16);
    uint32_t abase[4], am[4], bbase[4], bm[4];
    #pragma unroll
    for (int mf = 0; mf < 4; mf++) {
        uint32_t b = (a_row + mf * 16) * 128;
        abase[mf] = b;
        am[mf] = (b >> 3) & 0x70;
    }
    #pragma unroll
    for (int nfp = 0; nfp < 4; nfp++) {
        uint32_t b = (b_row + nfp * 16) * 128;
        bbase[nfp] = 16384 + b;
        bm[nfp] = (b >> 3) & 0x70;
    }

    load_stage(sb, 0, 0, m0, cb0, tid);
    load_stage(sb, 1, 1, m0, cb0, tid);

    // fragment ping-pong buffers
    uint32_t af[2][4][4], bf[2][8][2];

    for (int kc = 0; kc < NKC; kc++) {
        if (kc == NKC - 1) CP_WAIT0(); else CP_WAIT1();
        __syncthreads();

        uint32_t stg = sb + OFF_STG + (kc % NSTG) * STG_BYTES;

        // preload ks=0 fragments into buffer 0
        {
            const uint32_t ka = a_kb, kb = b_kb;
            #pragma unroll
            for (int mf = 0; mf < 4; mf++)
                ldsm_x4(af[0][mf], stg + abase[mf] + (ka ^ am[mf]));
            #pragma unroll
            for (int nfp = 0; nfp < 4; nfp++)
                ldsm_x4(&bf[0][nfp * 2][0], stg + bbase[nfp] + (kb ^ bm[nfp]));
        }

        // issue next stage's cp.async after the first fragment batch
        if (kc + 2 < NKC) load_stage(sb, (kc + 2) % NSTG, kc + 2, m0, cb0, tid);

        #pragma unroll
        for (int ks = 0; ks < 4; ks++) {
            const int cur = ks & 1;
            // prefetch next ks fragments into the other buffer BEFORE the
            // HMMA block, so LDSM latency overlaps 32 HMMAs
            if (ks < 3) {
                const int nxt = cur ^ 1;
                const uint32_t ka = (uint32_t)((ks + 1) * 32) + a_kb;
                const uint32_t kb = (uint32_t)((ks + 1) * 32) + b_kb;
                #pragma unroll
                for (int mf = 0; mf < 4; mf++)
                    ldsm_x4(af[nxt][mf], stg + abase[mf] + (ka ^ am[mf]));
                #pragma unroll
                for (int nfp = 0; nfp < 4; nfp++)
                    ldsm_x4(&bf[nxt][nfp * 2][0], stg + bbase[nfp] + (kb ^ bm[nfp]));
            }
            #pragma unroll
            for (int mf = 0; mf < 4; mf++)
                #pragma unroll
                for (int nf = 0; nf < 8; nf++)
                    hmma(acc[mf][nf], af[cur][mf], bf[cur][nf]);
        }
    }
    __syncthreads();   // done with stage buffers before smem reuse below

    // ---- epilogue: top-2 over this CTA's 256 cols per row ----
    float v1[8], v2[8];
    int   i1[8], i2[8];
    #pragma unroll
    for (int i = 0; i < 8; i++) {
        v1[i] = -3.4e38f; v2[i] = -3.4e38f; i1[i] = 0x7FFFFFF; i2[i] = 0x7FFFFFF;
    }

    #pragma unroll
    for (int mf = 0; mf < 4; mf++) {
        #pragma unroll
        for (int nf = 0; nf < 8; nf++) {
            int colb = warp_n * 64 + nf * 8 + (lane & 3) * 2;
            float s0 = acc[mf][nf][0] - es[colb];
            float s1 = acc[mf][nf][1] - es[colb + 1];
            float s2 = acc[mf][nf][2] - es[colb];
            float s3 = acc[mf][nf][3] - es[colb + 1];
            int sl0 = mf * 2, sl1 = mf * 2 + 1;
            upd2(s0, colb,     v1[sl0], i1[sl0], v2[sl0], i2[sl0]);
            upd2(s1, colb + 1, v1[sl0], i1[sl0], v2[sl0], i2[sl0]);
            upd2(s2, colb,     v1[sl1], i1[sl1], v2[sl1], i2[sl1]);
            upd2(s3, colb + 1, v1[sl1], i1[sl1], v2[sl1], i2[sl1]);
        }
    }
    #pragma unroll
    for (int off = 1; off <= 2; off <<= 1) {
        #pragma unroll
        for (int i = 0; i < 8; i++) {
            float ov1 = __shfl_xor_sync(0xFFFFFFFFu, v1[i], off);
            int   oi1 = __shfl_xor_sync(0xFFFFFFFFu, i1[i], off);
            float ov2 = __shfl_xor_sync(0xFFFFFFFFu, v2[i], off);
            int   oi2 = __shfl_xor_sync(0xFFFFFFFFu, i2[i], off);
            upd2(ov1, oi1, v1[i], i1[i], v2[i], i2[i]);
            upd2(ov2, oi2, v1[i], i1[i], v2[i], i2[i]);
        }
    }
    float* rv1 = reinterpret_cast<float*>(smem + OFF_RED);
    int*   ri1 = reinterpret_cast<int*>(smem + OFF_RED + 2048);
    float* rv2 = reinterpret_cast<float*>(smem + OFF_RED + 4096);
    int*   ri2 = reinterpret_cast<int*>(smem + OFF_RED + 6144);
    if ((lane & 3) == 0) {
        #pragma unroll
        for (int i = 0; i < 8; i++) {
            int row = warp_m * 64 + (i >> 1) * 16 + (lane >> 2) + (i & 1) * 8;
            rv1[row * 4 + warp_n] = v1[i];
            ri1[row * 4 + warp_n] = i1[i];
            rv2[row * 4 + warp_n] = v2[i];
            ri2[row * 4 + warp_n] = i2[i];
        }
    }
    __syncthreads();
    if (tid < BMT) {
        float bv1 = -3.4e38f, bv2 = -3.4e38f;
        int   bi1 = 0x7FFFFFF, bi2 = 0x7FFFFFF;
        #pragma unroll
        for (int w = 0; w < 4; w++) {
            upd2(rv1[tid * 4 + w], ri1[tid * 4 + w], bv1, bi1, bv2, bi2);
            upd2(rv2[tid * 4 + w], ri2[tid * 4 + w], bv1, bi1, bv2, bi2);
        }
        g_cand[blockIdx.y * NQ + m0 + tid] =
            make_float4(bv1, __int_as_float(cb0 + bi1), bv2, __int_as_float(cb0 + bi2));
    }
}

// ---------------------------------------------------------------------------
// Kernel 3: filter candidates, fp64-rescore ambiguous rows, gather output.
// ---------------------------------------------------------------------------
__global__ __launch_bounds__(256)
void finalize_kernel(const float* __restrict__ X, const float* __restrict__ E,
                     float* __restrict__ out, int write_idx) {
    int row = blockIdx.x;
    int t = threadIdx.x;
    __shared__ float4 ent[NCHUNK];
    __shared__ int    cidx[2 * NCHUNK];
    __shared__ double csc[2 * NCHUNK];
    __shared__ int    s_cnt, s_win;

    if (t < NCHUNK) ent[t] = g_cand[t * NQ + row];
    __syncthreads();

    if (t == 0) {
        float M = -3.4e38f;
        #pragma unroll
        for (int c = 0; c < NCHUNK; c++) M = fmaxf(M, ent[c].x);
        float thr = M - DELTA;
        int cnt = 0;
        for (int c = 0; c < NCHUNK; c++) {
            if (ent[c].x >= thr) cidx[cnt++] = __float_as_int(ent[c].y);
            if (ent[c].z >= thr) cidx[cnt++] = __float_as_int(ent[c].w);
        }
        s_cnt = cnt;
        if (cnt == 1) s_win = cidx[0];
    }
    __syncthreads();

    int cnt = s_cnt;
    if (cnt > 1) {
        int wid = t >> 5, lane = t & 31;
        for (int c = wid; c < cnt; c += 8) {
            const float* xr = X + (size_t)row * DD;
            const float* er = E + (size_t)cidx[c] * DD;
            double xe = 0.0, ee = 0.0;
            #pragma unroll
            for (int q = 0; q < DD / 32; q++) {
                double xv = (double)xr[q * 32 + lane];
                double ev = (double)er[q * 32 + lane];
                xe += xv * ev;
                ee += ev * ev;
            }
            double sc = 2.0 * xe - ee;
            #pragma unroll
            for (int o = 16; o; o >>= 1) sc += __shfl_down_sync(0xFFFFFFFFu, sc, o);
            if (lane == 0) csc[c] = sc;
        }
        __syncthreads();
        if (t == 0) {
            double bv = csc[0];
            int bi = cidx[0];
            for (int c = 1; c < cnt; c++) {
                if (csc[c] > bv || (csc[c] == bv && cidx[c] < bi)) {
                    bv = csc[c]; bi = cidx[c];
                }
            }
            s_win = bi;
        }
        __syncthreads();
    }

    int idx = s_win;
    if (t == 0 && write_idx) out[(size_t)NQ * DD + row] = (float)idx;
    if (t < 128) {
        float4 v = *reinterpret_cast<const float4*>(E + (size_t)idx * DD + t * 4);
        *reinterpret_cast<float4*>(out + (size_t)row * DD + t * 4) = v;
    }
}

// ---------------------------------------------------------------------------
extern "C" void kernel_launch(void* const* d_in, const int* in_sizes, int n_in,
                              void* d_out, int out_size) {
    const float* X = (const float*)d_in[0];
    const float* E = (const float*)d_in[1];
    float* out = (float*)d_out;

    static int attr_done = 0;
    if (!attr_done) {
        cudaFuncSetAttribute(vq_mma_kernel,
                             cudaFuncAttributeMaxDynamicSharedMemorySize, SMEM_TOTAL);
        attr_done = 1;
    }

    convert_kernel<<<NQ, 128>>>(X, E);
    vq_mma_kernel<<<dim3(NQ / BMT, NC / BNT), 256, SMEM_TOTAL>>>();
    int write_idx = (out_size >= NQ * DD + NQ) ? 1 : 0;
    finalize_kernel<<<NQ, 256>>>(X, E, out, write_idx);
}

// round 9
// speedup vs baseline: 1.1338x; 1.1338x over previous
#include <cuda_runtime.h>
#include <cuda_fp16.h>
#include <cstdint>

// SimpleCodebook VQ, R9: 1-product fp16 HMMA approx pass.  A operand is
// pre-permuted into mma fragment layout in GLOBAL memory (LDG.128 per tile,
// L1-served) so shared memory carries only B -> smem port no longer binds.
// Top-2 per (row,128-col chunk) candidates + exact fp64 rescore (DELTA=0.5).

#define NQ 8192
#define NC 8192
#define DD 512
#define BMT 128             // CTA tile M
#define BNT 128             // CTA tile N
#define BK  64              // K chunk (fp16)
#define NKC (DD / BK)       // 8
#define NCHUNK (NC / BNT)   // 64
#define DELTA 0.5f

#define NSTG 3
#define STG_BYTES 16384     // B only: 128 rows x 128B
#define OFF_ESQ 0           // 128 floats = 512B
#define OFF_RED 512         // 4 arrays x 128x4 x 4B = 8KB
#define OFF_STG 8704
#define SMEM_TOTAL (OFF_STG + NSTG * STG_BYTES)   // 57856 -> 2 CTAs/SM

// ---- device global scratch ----
// g_XF: A in fragment-packed layout. Per (mtile, ktile) 16x16 A-tile: 32
// lanes x 16B (uint4), mapping A[r][k] -> lane=(r&7)*4+((k&7)>>1),
// reg=(r>>3)+2*(k>>3), half=k&1.  uint4 index = (mtile*32 + ktile)*32 + lane.
__device__ uint4  g_XF[(NQ / 16) * (DD / 16) * 32];
__device__ __half g_E0[NC * DD];
__device__ float  g_esq[NC];
__device__ float4 g_cand[NCHUNK * NQ];   // (v1, idx1_bits, v2, idx2_bits)

static __device__ __forceinline__ uint32_t smem_u32(const void* p) {
    uint32_t a;
    asm("{ .reg .u64 t; cvta.to.shared.u64 t, %1; cvt.u32.u64 %0, t; }" : "=r"(a) : "l"(p));
    return a;
}
static __device__ __forceinline__ uint32_t swz(uint32_t o) { return o ^ ((o >> 3) & 0x70); }

static __device__ __forceinline__ void cp16(uint32_t dst, const void* src) {
    asm volatile("cp.async.cg.shared.global [%0], [%1], 16;" :: "r"(dst), "l"(src) : "memory");
}
#define CP_COMMIT() asm volatile("cp.async.commit_group;" ::: "memory")
#define CP_WAIT0()  asm volatile("cp.async.wait_group 0;" ::: "memory")
#define CP_WAIT1()  asm volatile("cp.async.wait_group 1;" ::: "memory")

static __device__ __forceinline__ void ldsm_x4(uint32_t* r, uint32_t addr) {
    asm volatile("ldmatrix.sync.aligned.m8n8.x4.shared.b16 {%0,%1,%2,%3}, [%4];"
                 : "=r"(r[0]), "=r"(r[1]), "=r"(r[2]), "=r"(r[3]) : "r"(addr));
}
static __device__ __forceinline__ void hmma(float* c, const uint32_t* a, const uint32_t* b) {
    asm volatile(
        "mma.sync.aligned.m16n8k16.row.col.f32.f16.f16.f32 "
        "{%0,%1,%2,%3}, {%4,%5,%6,%7}, {%8,%9}, {%0,%1,%2,%3};"
        : "+f"(c[0]), "+f"(c[1]), "+f"(c[2]), "+f"(c[3])
        : "r"(a[0]), "r"(a[1]), "r"(a[2]), "r"(a[3]), "r"(b[0]), "r"(b[1]));
}

// ---------------------------------------------------------------------------
// Kernel 1: g_XF = fragment-packed fp16(2x), g_E0 = fp16(e), esq = ||e||^2
// ---------------------------------------------------------------------------
__global__ void convert_kernel(const float* __restrict__ X, const float* __restrict__ E) {
    int row = blockIdx.x;
    int t = threadIdx.x;                     // 128, handles k = 4t..4t+3
    size_t base = (size_t)row * DD + t * 4;
    {
        float4 v = *reinterpret_cast<const float4*>(X + base);
        __half2 h01 = __floats2half2_rn(2.f * v.x, 2.f * v.y);
        __half2 h23 = __floats2half2_rn(2.f * v.z, 2.f * v.w);
        int mtile = row >> 4, i = row & 15;
        int k0 = t * 4, ktile = k0 >> 4, j0 = k0 & 15;
        int reg  = (i >> 3) + 2 * (j0 >> 3);     // same for all 4 k's (k0 % 4 == 0)
        int lane = (i & 7) * 4 + ((j0 & 7) >> 1);
        uint32_t* dst = reinterpret_cast<uint32_t*>(g_XF) +
                        ((size_t)(mtile * 32 + ktile) * 128);
        dst[lane * 4 + reg]       = *reinterpret_cast<uint32_t*>(&h01);
        dst[(lane + 1) * 4 + reg] = *reinterpret_cast<uint32_t*>(&h23);
    }
    {
        float4 v = *reinterpret_cast<const float4*>(E + base);
        __half2 h01 = __floats2half2_rn(v.x, v.y);
        __half2 h23 = __floats2half2_rn(v.z, v.w);
        *reinterpret_cast<__half2*>(&g_E0[base])     = h01;
        *reinterpret_cast<__half2*>(&g_E0[base + 2]) = h23;

        float sq = v.x * v.x + v.y * v.y + v.z * v.z + v.w * v.w;
        #pragma unroll
        for (int o = 16; o; o >>= 1) sq += __shfl_down_sync(0xFFFFFFFFu, sq, o);
        __shared__ float ws[4];
        if ((t & 31) == 0) ws[t >> 5] = sq;
        __syncthreads();
        if (t == 0) g_esq[row] = ws[0] + ws[1] + ws[2] + ws[3];
    }
}

// ---------------------------------------------------------------------------
// Kernel 2: approx HMMA GEMM + top-2 per (row, chunk). grid (64,64), 256 thr,
//           2 CTAs/SM.  A from global (fragment layout), B via smem/ldmatrix.
// ---------------------------------------------------------------------------
static __device__ __forceinline__ void load_stage_B(uint32_t sb, int s, int kc,
                                                    int cb0, int tid) {
    uint32_t stg = sb + OFF_STG + s * STG_BYTES;
    #pragma unroll
    for (int i = 0; i < 4; i++) {
        int cid = tid + i * 256;              // 0..1023
        int row = cid >> 3;
        int c16 = cid & 7;
        const __half* src = g_E0 + (size_t)(cb0 + row) * DD + kc * BK + c16 * 8;
        cp16(stg + swz((uint32_t)(row * 128 + c16 * 16)), src);
    }
    CP_COMMIT();
}

static __device__ __forceinline__ void upd2(float v, int i, float& v1, int& i1,
                                            float& v2, int& i2) {
    if (v > v1 || (v == v1 && i < i1)) {
        v2 = v1; i2 = i1; v1 = v; i1 = i;
    } else if (v > v2 || (v == v2 && i < i2)) {
        v2 = v; i2 = i;
    }
}

__global__ __launch_bounds__(256, 2)
void vq_mma_kernel() {
    extern __shared__ char smem[];
    const uint32_t sb = smem_u32(smem);
    const int tid = threadIdx.x;
    const int lane = tid & 31;
    const int wid = tid >> 5;
    const int warp_m = wid >> 2;         // 0..1  (64 rows each)
    const int warp_n = wid & 3;          // 0..3  (32 cols each)
    const int m0 = blockIdx.x * BMT;
    const int cb0 = blockIdx.y * BNT;

    float* es = reinterpret_cast<float*>(smem + OFF_ESQ);
    for (int i = tid; i < BNT; i += 256) es[i] = g_esq[cb0 + i];

    float acc[4][4][4];
    #pragma unroll
    for (int mf = 0; mf < 4; mf++)
        #pragma unroll
        for (int nf = 0; nf < 4; nf++)
            #pragma unroll
            for (int c = 0; c < 4; c++) acc[mf][nf][c] = 0.f;

    // A fragment base: uint4 index = (mtile*32 + ktile)*32 + lane
    const int mtile0 = (m0 >> 4) + warp_m * 4;
    const uint4* __restrict__ xf = g_XF;

    // B ldsm addressing (hoisted swizzle), B at stage offset 0
    const uint32_t b_row = (uint32_t)(warp_n * 32 + (lane >> 4) * 8 + (lane & 7));
    const uint32_t b_kb  = (uint32_t)(((lane >> 3) & 1) * 16);
    uint32_t bbase[2], bm[2];
    #pragma unroll
    for (int nfp = 0; nfp < 2; nfp++) {
        uint32_t b = (b_row + nfp * 16) * 128;
        bbase[nfp] = b;
        bm[nfp] = (b >> 3) & 0x70;
    }

    load_stage_B(sb, 0, 0, cb0, tid);
    load_stage_B(sb, 1, 1, cb0, tid);

    uint32_t af[2][4][4];

    for (int kc = 0; kc < NKC; kc++) {
        if (kc == NKC - 1) CP_WAIT0(); else CP_WAIT1();
        __syncthreads();

        // prefetch A fragments for ks=0 of this kc
        #pragma unroll
        for (int mf = 0; mf < 4; mf++) {
            uint4 a = __ldg(&xf[(size_t)((mtile0 + mf) * 32 + kc * 4) * 32 + lane]);
            af[0][mf][0] = a.x; af[0][mf][1] = a.y;
            af[0][mf][2] = a.z; af[0][mf][3] = a.w;
        }
        if (kc + 2 < NKC) load_stage_B(sb, (kc + 2) % NSTG, kc + 2, cb0, tid);

        uint32_t stg = sb + OFF_STG + (kc % NSTG) * STG_BYTES;

        #pragma unroll
        for (int ks = 0; ks < 4; ks++) {
            const int cur = ks & 1;
            if (ks < 3) {
                const int nxt = cur ^ 1;
                #pragma unroll
                for (int mf = 0; mf < 4; mf++) {
                    uint4 a = __ldg(&xf[(size_t)((mtile0 + mf) * 32 + kc * 4 + ks + 1) * 32 + lane]);
                    af[nxt][mf][0] = a.x; af[nxt][mf][1] = a.y;
                    af[nxt][mf][2] = a.z; af[nxt][mf][3] = a.w;
                }
            }
            const uint32_t kb = (uint32_t)(ks * 32) + b_kb;
            uint32_t b0[4][2];
            #pragma unroll
            for (int nfp = 0; nfp < 2; nfp++)
                ldsm_x4(&b0[nfp * 2][0], stg + bbase[nfp] + (kb ^ bm[nfp]));
            #pragma unroll
            for (int mf = 0; mf < 4; mf++)
                #pragma unroll
                for (int nf = 0; nf < 4; nf++)
                    hmma(acc[mf][nf], af[cur][mf], b0[nf]);
        }
    }
    __syncthreads();   // done with stage buffers before smem reuse below

    // ---- epilogue: top-2 over this CTA's 128 cols per row ----
    float v1[8], v2[8];
    int   i1[8], i2[8];
    #pragma unroll
    for (int i = 0; i < 8; i++) {
        v1[i] = -3.4e38f; v2[i] = -3.4e38f; i1[i] = 0x7FFFFFF; i2[i] = 0x7FFFFFF;
    }

    #pragma unroll
    for (int mf = 0; mf < 4; mf++) {
        #pragma unroll
        for (int nf = 0; nf < 4; nf++) {
            int colb = warp_n * 32 + nf * 8 + (lane & 3) * 2;
            float s0 = acc[mf][nf][0] - es[colb];
            float s1 = acc[mf][nf][1] - es[colb + 1];
            float s2 = acc[mf][nf][2] - es[colb];
            float s3 = acc[mf][nf][3] - es[colb + 1];
            int sl0 = mf * 2, sl1 = mf * 2 + 1;
            upd2(s0, colb,     v1[sl0], i1[sl0], v2[sl0], i2[sl0]);
            upd2(s1, colb + 1, v1[sl0], i1[sl0], v2[sl0], i2[sl0]);
            upd2(s2, colb,     v1[sl1], i1[sl1], v2[sl1], i2[sl1]);
            upd2(s3, colb + 1, v1[sl1], i1[sl1], v2[sl1], i2[sl1]);
        }
    }
    #pragma unroll
    for (int off = 1; off <= 2; off <<= 1) {
        #pragma unroll
        for (int i = 0; i < 8; i++) {
            float ov1 = __shfl_xor_sync(0xFFFFFFFFu, v1[i], off);
            int   oi1 = __shfl_xor_sync(0xFFFFFFFFu, i1[i], off);
            float ov2 = __shfl_xor_sync(0xFFFFFFFFu, v2[i], off);
            int   oi2 = __shfl_xor_sync(0xFFFFFFFFu, i2[i], off);
            upd2(ov1, oi1, v1[i], i1[i], v2[i], i2[i]);
            upd2(ov2, oi2, v1[i], i1[i], v2[i], i2[i]);
        }
    }
    float* rv1 = reinterpret_cast<float*>(smem + OFF_RED);
    int*   ri1 = reinterpret_cast<int*>(smem + OFF_RED + 2048);
    float* rv2 = reinterpret_cast<float*>(smem + OFF_RED + 4096);
    int*   ri2 = reinterpret_cast<int*>(smem + OFF_RED + 6144);
    if ((lane & 3) == 0) {
        #pragma unroll
        for (int i = 0; i < 8; i++) {
            int row = warp_m * 64 + (i >> 1) * 16 + (lane >> 2) + (i & 1) * 8;
            rv1[row * 4 + warp_n] = v1[i];
            ri1[row * 4 + warp_n] = i1[i];
            rv2[row * 4 + warp_n] = v2[i];
            ri2[row * 4 + warp_n] = i2[i];
        }
    }
    __syncthreads();
    if (tid < BMT) {
        float bv1 = -3.4e38f, bv2 = -3.4e38f;
        int   bi1 = 0x7FFFFFF, bi2 = 0x7FFFFFF;
        #pragma unroll
        for (int w = 0; w < 4; w++) {
            upd2(rv1[tid * 4 + w], ri1[tid * 4 + w], bv1, bi1, bv2, bi2);
            upd2(rv2[tid * 4 + w], ri2[tid * 4 + w], bv1, bi1, bv2, bi2);
        }
        g_cand[blockIdx.y * NQ + m0 + tid] =
            make_float4(bv1, __int_as_float(cb0 + bi1), bv2, __int_as_float(cb0 + bi2));
    }
}

// ---------------------------------------------------------------------------
// Kernel 3: filter candidates, fp64-rescore ambiguous rows, gather output.
// ---------------------------------------------------------------------------
__global__ __launch_bounds__(256)
void finalize_kernel(const float* __restrict__ X, const float* __restrict__ E,
                     float* __restrict__ out, int write_idx) {
    int row = blockIdx.x;
    int t = threadIdx.x;
    __shared__ float4 ent[NCHUNK];
    __shared__ int    cidx[2 * NCHUNK];
    __shared__ double csc[2 * NCHUNK];
    __shared__ int    s_cnt, s_win;

    if (t < NCHUNK) ent[t] = g_cand[t * NQ + row];
    __syncthreads();

    if (t == 0) {
        float M = -3.4e38f;
        #pragma unroll
        for (int c = 0; c < NCHUNK; c++) M = fmaxf(M, ent[c].x);
        float thr = M - DELTA;
        int cnt = 0;
        for (int c = 0; c < NCHUNK; c++) {
            if (ent[c].x >= thr) cidx[cnt++] = __float_as_int(ent[c].y);
            if (ent[c].z >= thr) cidx[cnt++] = __float_as_int(ent[c].w);
        }
        s_cnt = cnt;
        if (cnt == 1) s_win = cidx[0];
    }
    __syncthreads();

    int cnt = s_cnt;
    if (cnt > 1) {
        int wid = t >> 5, lane = t & 31;
        for (int c = wid; c < cnt; c += 8) {
            const float* xr = X + (size_t)row * DD;
            const float* er = E + (size_t)cidx[c] * DD;
            double xe = 0.0, ee = 0.0;
            #pragma unroll
            for (int q = 0; q < DD / 32; q++) {
                double xv = (double)xr[q * 32 + lane];
                double ev = (double)er[q * 32 + lane];
                xe += xv * ev;
                ee += ev * ev;
            }
            double sc = 2.0 * xe - ee;
            #pragma unroll
            for (int o = 16; o; o >>= 1) sc += __shfl_down_sync(0xFFFFFFFFu, sc, o);
            if (lane == 0) csc[c] = sc;
        }
        __syncthreads();
        if (t == 0) {
            double bv = csc[0];
            int bi = cidx[0];
            for (int c = 1; c < cnt; c++) {
                if (csc[c] > bv || (csc[c] == bv && cidx[c] < bi)) {
                    bv = csc[c]; bi = cidx[c];
                }
            }
            s_win = bi;
        }
        __syncthreads();
    }

    int idx = s_win;
    if (t == 0 && write_idx) out[(size_t)NQ * DD + row] = (float)idx;
    if (t < 128) {
        float4 v = *reinterpret_cast<const float4*>(E + (size_t)idx * DD + t * 4);
        *reinterpret_cast<float4*>(out + (size_t)row * DD + t * 4) = v;
    }
}

// ---------------------------------------------------------------------------
extern "C" void kernel_launch(void* const* d_in, const int* in_sizes, int n_in,
                              void* d_out, int out_size) {
    const float* X = (const float*)d_in[0];
    const float* E = (const float*)d_in[1];
    float* out = (float*)d_out;

    static int attr_done = 0;
    if (!attr_done) {
        cudaFuncSetAttribute(vq_mma_kernel,
                             cudaFuncAttributeMaxDynamicSharedMemorySize, SMEM_TOTAL);
        attr_done = 1;
    }

    convert_kernel<<<NQ, 128>>>(X, E);
    vq_mma_kernel<<<dim3(NQ / BMT, NC / BNT), 256, SMEM_TOTAL>>>();
    int write_idx = (out_size >= NQ * DD + NQ) ? 1 : 0;
    finalize_kernel<<<NQ, 256>>>(X, E, out, write_idx);
}

// round 10
// speedup vs baseline: 1.4041x; 1.2384x over previous
#include <cuda_runtime.h>
#include <cstdint>

// SimpleCodebook VQ, R10: int8 IMMA (m16n8k32.s8) approximate pass + exact
// fp64 rescore of ambiguous rows.
//   x_q = rn(x/ax), e_q = rn(e/ae)  per-row symmetric scales (int32 dot EXACT)
//   approx[n,k] = (2*ax_n*ae_k)*dot_int - ||e_k||^2 ; |approx-true| <~ 4.2
//   Candidates: top-2 per (row, 64-col group), filter at M - DELTA (=8),
//   fp64 rescore when >1 survivor.

#define NQ 8192
#define NC 8192
#define DD 512
#define BMT 128             // CTA tile M
#define BNT 128             // CTA tile N
#define BK  128             // K chunk (int8) -> 128B rows
#define NKC (DD / BK)       // 4
#define NGRP (2 * (NC / BNT))  // 128 candidate groups per row (64 cols each)
#define DELTA 8.0f

#define NSTG 3
#define STG_BYTES 32768     // A(16K) + B(16K)
#define OFF_ESQ 0           // 128 floats
#define OFF_AE  512         // 128 floats
#define OFF_AX  1024        // 128 floats
#define OFF_RED 1536        // 4 arrays x 128x4 x 4B = 8KB
#define OFF_STG 9728
#define SMEM_TOTAL (OFF_STG + NSTG * STG_BYTES)   // 108032 -> 2 CTAs/SM

// ---- device global scratch ----
__device__ uint8_t g_Xq[NQ * DD];
__device__ uint8_t g_Eq[NC * DD];
__device__ float   g_ax[NQ];       // 2 * max|x_row| / 127
__device__ float   g_ae[NC];       // max|e_row| / 127
__device__ float   g_esq[NC];
__device__ float4  g_cand[NGRP * NQ];   // (v1, idx1_bits, v2, idx2_bits)

static __device__ __forceinline__ uint32_t smem_u32(const void* p) {
    uint32_t a;
    asm("{ .reg .u64 t; cvta.to.shared.u64 t, %1; cvt.u32.u64 %0, t; }" : "=r"(a) : "l"(p));
    return a;
}
static __device__ __forceinline__ uint32_t swz(uint32_t o) { return o ^ ((o >> 3) & 0x70); }

static __device__ __forceinline__ void cp16(uint32_t dst, const void* src) {
    asm volatile("cp.async.cg.shared.global [%0], [%1], 16;" :: "r"(dst), "l"(src) : "memory");
}
#define CP_COMMIT() asm volatile("cp.async.commit_group;" ::: "memory")
#define CP_WAIT0()  asm volatile("cp.async.wait_group 0;" ::: "memory")
#define CP_WAIT1()  asm volatile("cp.async.wait_group 1;" ::: "memory")

static __device__ __forceinline__ void ldsm_x4(uint32_t* r, uint32_t addr) {
    asm volatile("ldmatrix.sync.aligned.m8n8.x4.shared.b16 {%0,%1,%2,%3}, [%4];"
                 : "=r"(r[0]), "=r"(r[1]), "=r"(r[2]), "=r"(r[3]) : "r"(addr));
}
static __device__ __forceinline__ void imma(int* c, const uint32_t* a, const uint32_t* b) {
    asm volatile(
        "mma.sync.aligned.m16n8k32.row.col.s32.s8.s8.s32 "
        "{%0,%1,%2,%3}, {%4,%5,%6,%7}, {%8,%9}, {%0,%1,%2,%3};"
        : "+r"(c[0]), "+r"(c[1]), "+r"(c[2]), "+r"(c[3])
        : "r"(a[0]), "r"(a[1]), "r"(a[2]), "r"(a[3]), "r"(b[0]), "r"(b[1]));
}

static __device__ __forceinline__ int q8(float v, float inv) {
    int q = __float2int_rn(v * inv);
    return max(-127, min(127, q));
}

// ---------------------------------------------------------------------------
// Kernel 1: per-row quantize X (x2 folded into ax) and E; esq = ||e||^2
// ---------------------------------------------------------------------------
__global__ void convert_kernel(const float* __restrict__ X, const float* __restrict__ E) {
    int row = blockIdx.x;
    int t = threadIdx.x;                     // 128
    size_t base = (size_t)row * DD + t * 4;
    __shared__ float wmx[4], wme[4], wsq[4];
    __shared__ float s_ix, s_ie;

    float4 vx = *reinterpret_cast<const float4*>(X + base);
    float4 ve = *reinterpret_cast<const float4*>(E + base);

    float mx = fmaxf(fmaxf(fabsf(vx.x), fabsf(vx.y)), fmaxf(fabsf(vx.z), fabsf(vx.w)));
    float me = fmaxf(fmaxf(fabsf(ve.x), fabsf(ve.y)), fmaxf(fabsf(ve.z), fabsf(ve.w)));
    float sq = ve.x * ve.x + ve.y * ve.y + ve.z * ve.z + ve.w * ve.w;
    #pragma unroll
    for (int o = 16; o; o >>= 1) {
        mx = fmaxf(mx, __shfl_xor_sync(0xFFFFFFFFu, mx, o));
        me = fmaxf(me, __shfl_xor_sync(0xFFFFFFFFu, me, o));
        sq += __shfl_down_sync(0xFFFFFFFFu, sq, o);
    }
    if ((t & 31) == 0) { wmx[t >> 5] = mx; wme[t >> 5] = me; wsq[t >> 5] = sq; }
    __syncthreads();
    if (t == 0) {
        float Mx = fmaxf(fmaxf(wmx[0], wmx[1]), fmaxf(wmx[2], wmx[3]));
        float Me = fmaxf(fmaxf(wme[0], wme[1]), fmaxf(wme[2], wme[3]));
        Mx = fmaxf(Mx, 1e-20f);
        Me = fmaxf(Me, 1e-20f);
        g_ax[row] = 2.0f * Mx / 127.0f;
        g_ae[row] = Me / 127.0f;
        g_esq[row] = wsq[0] + wsq[1] + wsq[2] + wsq[3];
        s_ix = 127.0f / Mx;
        s_ie = 127.0f / Me;
    }
    __syncthreads();
    float ix = s_ix, ie = s_ie;

    uint32_t px = (uint32_t)(q8(vx.x, ix) & 0xFF)
                | ((uint32_t)(q8(vx.y, ix) & 0xFF) << 8)
                | ((uint32_t)(q8(vx.z, ix) & 0xFF) << 16)
                | ((uint32_t)(q8(vx.w, ix) & 0xFF) << 24);
    uint32_t pe = (uint32_t)(q8(ve.x, ie) & 0xFF)
                | ((uint32_t)(q8(ve.y, ie) & 0xFF) << 8)
                | ((uint32_t)(q8(ve.z, ie) & 0xFF) << 16)
                | ((uint32_t)(q8(ve.w, ie) & 0xFF) << 24);
    *reinterpret_cast<uint32_t*>(g_Xq + base) = px;
    *reinterpret_cast<uint32_t*>(g_Eq + base) = pe;
}

// ---------------------------------------------------------------------------
// Kernel 2: IMMA GEMM + top-2 per (row, 64-col group). grid (64,64), 256 thr,
//           2 CTAs/SM.
// ---------------------------------------------------------------------------
static __device__ __forceinline__ void load_stage(uint32_t sb, int s, int kc,
                                                  int m0, int cb0, int tid) {
    uint32_t stg = sb + OFF_STG + s * STG_BYTES;
    #pragma unroll
    for (int i = 0; i < 4; i++) {
        int cid = tid + i * 256;              // 0..1023
        int row = cid >> 3;
        int c16 = cid & 7;
        const uint8_t* src = g_Xq + (size_t)(m0 + row) * DD + kc * BK + c16 * 16;
        cp16(stg + swz((uint32_t)(row * 128 + c16 * 16)), src);
    }
    #pragma unroll
    for (int i = 0; i < 4; i++) {
        int cid = tid + i * 256;
        int row = cid >> 3;
        int c16 = cid & 7;
        const uint8_t* src = g_Eq + (size_t)(cb0 + row) * DD + kc * BK + c16 * 16;
        cp16(stg + 16384 + swz((uint32_t)(row * 128 + c16 * 16)), src);
    }
    CP_COMMIT();
}

static __device__ __forceinline__ void upd2(float v, int i, float& v1, int& i1,
                                            float& v2, int& i2) {
    if (v > v1 || (v == v1 && i < i1)) {
        v2 = v1; i2 = i1; v1 = v; i1 = i;
    } else if (v > v2 || (v == v2 && i < i2)) {
        v2 = v; i2 = i;
    }
}

__global__ __launch_bounds__(256, 2)
void vq_mma_kernel() {
    extern __shared__ char smem[];
    const uint32_t sb = smem_u32(smem);
    const int tid = threadIdx.x;
    const int lane = tid & 31;
    const int wid = tid >> 5;
    const int warp_m = wid >> 2;         // 0..1  (64 rows each)
    const int warp_n = wid & 3;          // 0..3  (32 cols each)
    const int m0 = blockIdx.x * BMT;
    const int cb0 = blockIdx.y * BNT;

    float* ses = reinterpret_cast<float*>(smem + OFF_ESQ);
    float* sae = reinterpret_cast<float*>(smem + OFF_AE);
    float* sax = reinterpret_cast<float*>(smem + OFF_AX);
    if (tid < BNT) {
        ses[tid] = g_esq[cb0 + tid];
        sae[tid] = g_ae[cb0 + tid];
    } else {
        int r = tid - BNT;
        sax[r] = g_ax[m0 + r];
        sax[r + 64] = g_ax[m0 + 64 + r];
    }

    int acc[4][4][4];
    #pragma unroll
    for (int mf = 0; mf < 4; mf++)
        #pragma unroll
        for (int nf = 0; nf < 4; nf++)
            #pragma unroll
            for (int c = 0; c < 4; c++) acc[mf][nf][c] = 0;

    // hoisted swizzle: addr = stg + base + (k ^ m), m = ((row*128)>>3)&0x70
    const uint32_t a_row = (uint32_t)(warp_m * 64 + (lane & 15));
    const uint32_t a_kb  = (uint32_t)((lane >> 4) * 16);
    const uint32_t b_row = (uint32_t)(warp_n * 32 + (lane >> 4) * 8 + (lane & 7));
    const uint32_t b_kb  = (uint32_t)(((lane >> 3) & 1) * 16);
    uint32_t abase[4], am[4], bbase[2], bm[2];
    #pragma unroll
    for (int mf = 0; mf < 4; mf++) {
        uint32_t b = (a_row + mf * 16) * 128;
        abase[mf] = b;
        am[mf] = (b >> 3) & 0x70;
    }
    #pragma unroll
    for (int nfp = 0; nfp < 2; nfp++) {
        uint32_t b = (b_row + nfp * 16) * 128;
        bbase[nfp] = 16384 + b;
        bm[nfp] = (b >> 3) & 0x70;
    }

    load_stage(sb, 0, 0, m0, cb0, tid);
    load_stage(sb, 1, 1, m0, cb0, tid);

    for (int kc = 0; kc < NKC; kc++) {
        if (kc == NKC - 1) CP_WAIT0(); else CP_WAIT1();
        __syncthreads();
        if (kc + 2 < NKC) load_stage(sb, (kc + 2) % NSTG, kc + 2, m0, cb0, tid);

        uint32_t stg = sb + OFF_STG + (kc % NSTG) * STG_BYTES;

        #pragma unroll
        for (int ks = 0; ks < 4; ks++) {            // 32 int8 per ks
            const uint32_t ka = (uint32_t)(ks * 32) + a_kb;
            const uint32_t kb = (uint32_t)(ks * 32) + b_kb;
            uint32_t a0[4][4], b0[4][2];
            #pragma unroll
            for (int mf = 0; mf < 4; mf++)
                ldsm_x4(a0[mf], stg + abase[mf] + (ka ^ am[mf]));
            #pragma unroll
            for (int nfp = 0; nfp < 2; nfp++)
                ldsm_x4(&b0[nfp * 2][0], stg + bbase[nfp] + (kb ^ bm[nfp]));
            #pragma unroll
            for (int mf = 0; mf < 4; mf++)
                #pragma unroll
                for (int nf = 0; nf < 4; nf++)
                    imma(acc[mf][nf], a0[mf], b0[nf]);
        }
    }
    __syncthreads();   // done with stage buffers before smem reuse below

    // ---- epilogue: top-2 over 32-col warp slice per row, then merge ----
    float v1[8], v2[8];
    int   i1[8], i2[8];
    #pragma unroll
    for (int i = 0; i < 8; i++) {
        v1[i] = -3.4e38f; v2[i] = -3.4e38f; i1[i] = 0x7FFFFFF; i2[i] = 0x7FFFFFF;
    }
    float axv[2][4];
    #pragma unroll
    for (int mf = 0; mf < 4; mf++) {
        axv[0][mf] = sax[warp_m * 64 + mf * 16 + (lane >> 2)];
        axv[1][mf] = sax[warp_m * 64 + mf * 16 + (lane >> 2) + 8];
    }

    #pragma unroll
    for (int mf = 0; mf < 4; mf++) {
        #pragma unroll
        for (int nf = 0; nf < 4; nf++) {
            int colb = warp_n * 32 + nf * 8 + (lane & 3) * 2;
            float ae0 = sae[colb], ae1 = sae[colb + 1];
            float q0 = ses[colb], q1 = ses[colb + 1];
            float s0 = axv[0][mf] * ae0 * (float)acc[mf][nf][0] - q0;
            float s1 = axv[0][mf] * ae1 * (float)acc[mf][nf][1] - q1;
            float s2 = axv[1][mf] * ae0 * (float)acc[mf][nf][2] - q0;
            float s3 = axv[1][mf] * ae1 * (float)acc[mf][nf][3] - q1;
            int sl0 = mf * 2, sl1 = mf * 2 + 1;
            upd2(s0, colb,     v1[sl0], i1[sl0], v2[sl0], i2[sl0]);
            upd2(s1, colb + 1, v1[sl0], i1[sl0], v2[sl0], i2[sl0]);
            upd2(s2, colb,     v1[sl1], i1[sl1], v2[sl1], i2[sl1]);
            upd2(s3, colb + 1, v1[sl1], i1[sl1], v2[sl1], i2[sl1]);
        }
    }
    #pragma unroll
    for (int off = 1; off <= 2; off <<= 1) {
        #pragma unroll
        for (int i = 0; i < 8; i++) {
            float ov1 = __shfl_xor_sync(0xFFFFFFFFu, v1[i], off);
            int   oi1 = __shfl_xor_sync(0xFFFFFFFFu, i1[i], off);
            float ov2 = __shfl_xor_sync(0xFFFFFFFFu, v2[i], off);
            int   oi2 = __shfl_xor_sync(0xFFFFFFFFu, i2[i], off);
            upd2(ov1, oi1, v1[i], i1[i], v2[i], i2[i]);
            upd2(ov2, oi2, v1[i], i1[i], v2[i], i2[i]);
        }
    }
    float* rv1 = reinterpret_cast<float*>(smem + OFF_RED);
    int*   ri1 = reinterpret_cast<int*>(smem + OFF_RED + 2048);
    float* rv2 = reinterpret_cast<float*>(smem + OFF_RED + 4096);
    int*   ri2 = reinterpret_cast<int*>(smem + OFF_RED + 6144);
    if ((lane & 3) == 0) {
        #pragma unroll
        for (int i = 0; i < 8; i++) {
            int row = warp_m * 64 + (i >> 1) * 16 + (lane >> 2) + (i & 1) * 8;
            rv1[row * 4 + warp_n] = v1[i];
            ri1[row * 4 + warp_n] = i1[i];
            rv2[row * 4 + warp_n] = v2[i];
            ri2[row * 4 + warp_n] = i2[i];
        }
    }
    __syncthreads();
    // merge warp_n pairs {0,1} and {2,3} -> top-2 per 64-col group
    if (tid < 2 * BMT) {
        int row = tid >> 1;
        int g = tid & 1;                       // group: cols g*64 .. g*64+63
        float bv1 = -3.4e38f, bv2 = -3.4e38f;
        int   bi1 = 0x7FFFFFF, bi2 = 0x7FFFFFF;
        #pragma unroll
        for (int w = 0; w < 2; w++) {
            int wn = g * 2 + w;
            upd2(rv1[row * 4 + wn], ri1[row * 4 + wn], bv1, bi1, bv2, bi2);
            upd2(rv2[row * 4 + wn], ri2[row * 4 + wn], bv1, bi1, bv2, bi2);
        }
        g_cand[(blockIdx.y * 2 + g) * NQ + m0 + row] =
            make_float4(bv1, __int_as_float(cb0 + bi1), bv2, __int_as_float(cb0 + bi2));
    }
}

// ---------------------------------------------------------------------------
// Kernel 3: filter candidates, fp64-rescore ambiguous rows, gather output.
// ---------------------------------------------------------------------------
__global__ __launch_bounds__(256)
void finalize_kernel(const float* __restrict__ X, const float* __restrict__ E,
                     float* __restrict__ out, int write_idx) {
    int row = blockIdx.x;
    int t = threadIdx.x;
    __shared__ float4 ent[NGRP];
    __shared__ int    cidx[2 * NGRP];
    __shared__ double csc[2 * NGRP];
    __shared__ int    s_cnt, s_win;

    if (t < NGRP) ent[t] = g_cand[t * NQ + row];
    __syncthreads();

    if (t == 0) {
        float M = -3.4e38f;
        for (int c = 0; c < NGRP; c++) M = fmaxf(M, ent[c].x);
        float thr = M - DELTA;
        int cnt = 0;
        for (int c = 0; c < NGRP; c++) {
            if (ent[c].x >= thr) cidx[cnt++] = __float_as_int(ent[c].y);
            if (ent[c].z >= thr) cidx[cnt++] = __float_as_int(ent[c].w);
        }
        s_cnt = cnt;
        if (cnt == 1) s_win = cidx[0];
    }
    __syncthreads();

    int cnt = s_cnt;
    if (cnt > 1) {
        int wid = t >> 5, lane = t & 31;
        for (int c = wid; c < cnt; c += 8) {
            const float* xr = X + (size_t)row * DD;
            const float* er = E + (size_t)cidx[c] * DD;
            double xe = 0.0, ee = 0.0;
            #pragma unroll
            for (int q = 0; q < DD / 32; q++) {
                double xv = (double)xr[q * 32 + lane];
                double ev = (double)er[q * 32 + lane];
                xe += xv * ev;
                ee += ev * ev;
            }
            double sc = 2.0 * xe - ee;
            #pragma unroll
            for (int o = 16; o; o >>= 1) sc += __shfl_down_sync(0xFFFFFFFFu, sc, o);
            if (lane == 0) csc[c] = sc;
        }
        __syncthreads();
        if (t == 0) {
            double bv = csc[0];
            int bi = cidx[0];
            for (int c = 1; c < cnt; c++) {
                if (csc[c] > bv || (csc[c] == bv && cidx[c] < bi)) {
                    bv = csc[c]; bi = cidx[c];
                }
            }
            s_win = bi;
        }
        __syncthreads();
    }

    int idx = s_win;
    if (t == 0 && write_idx) out[(size_t)NQ * DD + row] = (float)idx;
    if (t < 128) {
        float4 v = *reinterpret_cast<const float4*>(E + (size_t)idx * DD + t * 4);
        *reinterpret_cast<float4*>(out + (size_t)row * DD + t * 4) = v;
    }
}

// ---------------------------------------------------------------------------
extern "C" void kernel_launch(void* const* d_in, const int* in_sizes, int n_in,
                              void* d_out, int out_size) {
    const float* X = (const float*)d_in[0];
    const float* E = (const float*)d_in[1];
    float* out = (float*)d_out;

    static int attr_done = 0;
    if (!attr_done) {
        cudaFuncSetAttribute(vq_mma_kernel,
                             cudaFuncAttributeMaxDynamicSharedMemorySize, SMEM_TOTAL);
        attr_done = 1;
    }

    convert_kernel<<<NQ, 128>>>(X, E);
    vq_mma_kernel<<<dim3(NQ / BMT, NC / BNT), 256, SMEM_TOTAL>>>();
    int write_idx = (out_size >= NQ * DD + NQ) ? 1 : 0;
    finalize_kernel<<<NQ, 256>>>(X, E, out, write_idx);
}